// round 15
// baseline (speedup 1.0000x reference)
#include <cuda_runtime.h>
#include <math.h>

#define BATCH 2
#define NP    4096
#define HH    128
#define WW    128
#define KK    8
#define RAD   0.05f
#define RAD2  (RAD * RAD)
#define TILE  8
#define TX    (WW / TILE)    // 16
#define TYN   (HH / TILE)    // 16
#define LPP   4
#define NPIX  (TILE * TILE)  // 64
#define THREADS (NPIX * LPP) // 256
#define PPT   (NP / THREADS) // 16 points per thread
#define CAPQ  512            // per-quadrant smem capacity (~3x max observed)

#define ZINF 3.0e38f

__global__ void __launch_bounds__(THREADS) raster_fused(
        const float* __restrict__ pts,
        const float* __restrict__ Rm,
        const float* __restrict__ Tv,
        const float* __restrict__ Fc,
        float* __restrict__ out) {
    __shared__ float4 sc[4][CAPQ];   // 32 KB: per-quadrant candidate lists
    __shared__ int s_cnt[4];

    const int bx = blockIdx.x, by = blockIdx.y, b = blockIdx.z;
    const int tid = threadIdx.x;

    if (tid < 4) s_cnt[tid] = 0;
    __syncthreads();

    // Uniform per-batch camera params (broadcast loads)
    const float* Rb = Rm + b * 9;
    const float* Tb = Tv + b * 3;
    const float r00 = Rb[0], r01 = Rb[1], r02 = Rb[2];
    const float r10 = Rb[3], r11 = Rb[4], r12 = Rb[5];
    const float r20 = Rb[6], r21 = Rb[7], r22 = Rb[8];
    const float t0 = Tb[0], t1 = Tb[1], t2 = Tb[2];
    const float f  = Fc[b];

    // Quadrant NDC bboxes (gx decreases with pixel x). Quadrant qx=0: px
    // [8bx, 8bx+3]; qx=1: [8bx+4, 8bx+7]. Same for y.
    const float base_x = (float)(TILE * bx);
    const float base_y = (float)(TILE * by);
    const float q0x_hi = 1.0f - (base_x + 0.5f) * (1.0f / 64.0f) + RAD;
    const float q0x_lo = 1.0f - (base_x + 3.5f) * (1.0f / 64.0f) - RAD;
    const float q1x_hi = 1.0f - (base_x + 4.5f) * (1.0f / 64.0f) + RAD;
    const float q1x_lo = 1.0f - (base_x + 7.5f) * (1.0f / 64.0f) - RAD;
    const float q0y_hi = 1.0f - (base_y + 0.5f) * (1.0f / 64.0f) + RAD;
    const float q0y_lo = 1.0f - (base_y + 3.5f) * (1.0f / 64.0f) - RAD;
    const float q1y_hi = 1.0f - (base_y + 4.5f) * (1.0f / 64.0f) + RAD;
    const float q1y_lo = 1.0f - (base_y + 7.5f) * (1.0f / 64.0f) - RAD;

    // ====== Phase 1: redundant transform; thread owns 16 CONSECUTIVE points ==
    {
        const float4* pb4 = (const float4*)(pts + (size_t)b * NP * 3);
        int p0i = tid * PPT;
#pragma unroll
        for (int it = 0; it < PPT / 4; it++) {
            int pbase = p0i + it * 4;
            int f4 = (pbase * 3) >> 2;        // pbase*3 divisible by 4
            float4 A = pb4[f4 + 0];
            float4 Bv = pb4[f4 + 1];
            float4 C = pb4[f4 + 2];
            float px3[4], py3[4], pz3[4];
            px3[0] = A.x;  py3[0] = A.y;  pz3[0] = A.z;
            px3[1] = A.w;  py3[1] = Bv.x; pz3[1] = Bv.y;
            px3[2] = Bv.z; py3[2] = Bv.w; pz3[2] = C.x;
            px3[3] = C.y;  py3[3] = C.z;  pz3[3] = C.w;
#pragma unroll
            for (int i = 0; i < 4; i++) {
                float p0 = px3[i], p1 = py3[i], p2 = pz3[i];
                // row-vector: v[j] = sum_i p[i]*R[i][j] + T[j]  (same expr as ref)
                float xv = p0 * r00 + p1 * r10 + p2 * r20 + t0;
                float yv = p0 * r01 + p1 * r11 + p2 * r21 + t1;
                float zv = p0 * r02 + p1 * r12 + p2 * r22 + t2;
                float x = f * xv / zv;        // IEEE div, matches reference
                float y = f * yv / zv;
                if (zv > 0.0f) {
                    bool x0 = (x > q0x_lo) && (x < q0x_hi);
                    bool x1 = (x > q1x_lo) && (x < q1x_hi);
                    bool y0 = (y > q0y_lo) && (y < q0y_hi);
                    bool y1 = (y > q1y_lo) && (y < q1y_hi);
                    if ((x0 | x1) & (y0 | y1)) {
                        float4 rec = make_float4(x, y, zv, (float)(pbase + i));
                        if (x0 & y0) { int p_ = atomicAdd(&s_cnt[0], 1); if (p_ < CAPQ) sc[0][p_] = rec; }
                        if (x1 & y0) { int p_ = atomicAdd(&s_cnt[1], 1); if (p_ < CAPQ) sc[1][p_] = rec; }
                        if (x0 & y1) { int p_ = atomicAdd(&s_cnt[2], 1); if (p_ < CAPQ) sc[2][p_] = rec; }
                        if (x1 & y1) { int p_ = atomicAdd(&s_cnt[3], 1); if (p_ < CAPQ) sc[3][p_] = rec; }
                    }
                }
            }
        }
    }
    __syncthreads();

    // ====== Phase 2: raster — pixel scans ONLY its quadrant list =============
    const int grp = tid >> 2;      // pixel 0..63
    const int sub = tid & 3;       // lane within pixel
    const int lx = grp & (TILE - 1), ly = grp / TILE;
    const int q = (ly >> 2) * 2 + (lx >> 2);
    const int n = min(s_cnt[q], CAPQ);
    const float4* __restrict__ ql = sc[q];

    const int px = bx * TILE + lx;
    const int py = by * TILE + ly;
    const float gx = 1.0f - (px + 0.5f) * (1.0f / 64.0f);
    const float gy = 1.0f - (py + 0.5f) * (1.0f / 64.0f);

    float zb[KK];
#pragma unroll
    for (int k = 0; k < KK; k++) zb[k] = ZINF;

    // ---- Pass 1: branch-free FMNMX ladder, lane scans j%4==sub -------------
    for (int j = sub; j < n; j += LPP) {
        float4 c = ql[j];
        float dx = gx - c.x;
        float dy = gy - c.y;
        float d2 = fmaf(dx, dx, dy * dy);
        float key = (d2 < RAD2) ? c.z : ZINF;
#pragma unroll
        for (int k = 0; k < KK; k++) {
            float lo = fminf(zb[k], key);
            key = fmaxf(zb[k], key);
            zb[k] = lo;
        }
    }

    // ---- merge 4 sorted lists: two bitonic-merge rounds (xor 1, xor 2) ------
#pragma unroll
    for (int d = 1; d <= 2; d <<= 1) {
        float L[KK];
#pragma unroll
        for (int k = 0; k < KK; k++) {
            float bk = __shfl_xor_sync(0xffffffffu, zb[KK - 1 - k], d);
            L[k] = fminf(zb[k], bk);          // lower half of bitonic merge
        }
#define CE(a, b2) { float lo = fminf(L[a], L[b2]); float hi = fmaxf(L[a], L[b2]); L[a] = lo; L[b2] = hi; }
        CE(0, 4) CE(1, 5) CE(2, 6) CE(3, 7)
        CE(0, 2) CE(1, 3) CE(4, 6) CE(5, 7)
        CE(0, 1) CE(2, 3) CE(4, 5) CE(6, 7)
#undef CE
#pragma unroll
        for (int k = 0; k < KK; k++) zb[k] = L[k];
    }
    const float z7 = zb[KK - 1];

    float db[KK], ib[KK];
#pragma unroll
    for (int k = 0; k < KK; k++) { db[k] = -1.0f; ib[k] = -1.0f; }

    // ---- Pass 2: sparse equality fill of d2/idx (z values distinct) ---------
    for (int j = sub; j < n; j += LPP) {
        float4 c = ql[j];
        float dx = gx - c.x;
        float dy = gy - c.y;
        float d2 = fmaf(dx, dx, dy * dy);
        if (d2 < RAD2 && c.z <= z7) {
#pragma unroll
            for (int k = 0; k < KK; k++) {
                if (c.z == zb[k]) { db[k] = d2; ib[k] = c.w; }
            }
        }
    }

    // ---- combine lane fills (unfilled = -1, filled >= 0 => max) -------------
#pragma unroll
    for (int d = 1; d <= 2; d <<= 1) {
#pragma unroll
        for (int k = 0; k < KK; k++) {
            db[k] = fmaxf(db[k], __shfl_xor_sync(0xffffffffu, db[k], d));
            ib[k] = fmaxf(ib[k], __shfl_xor_sync(0xffffffffu, ib[k], d));
        }
    }

    // ---- Output: [idx | zbuf | dists], each [B,H,W,K]; lanes split k --------
    const int N = BATCH * HH * WW * KK;
    const int obase = ((b * HH + py) * WW + px) * KK;
#pragma unroll
    for (int k2 = 0; k2 < KK / LPP; k2++) {
        int k = sub * (KK / LPP) + k2;
        bool v = zb[k] < ZINF;
        out[obase + k]         = v ? ib[k] : -1.0f;
        out[N + obase + k]     = v ? zb[k] : -1.0f;
        out[2 * N + obase + k] = v ? db[k] : -1.0f;
    }
}

// ---------------------------------------------------------------------------
extern "C" void kernel_launch(void* const* d_in, const int* in_sizes, int n_in,
                              void* d_out, int out_size) {
    const float* pts = (const float*)d_in[0];
    const float* Rm  = (const float*)d_in[1];
    const float* Tv  = (const float*)d_in[2];
    const float* Fc  = (const float*)d_in[3];
    float* out = (float*)d_out;

    raster_fused<<<dim3(TX, TYN, BATCH), THREADS>>>(pts, Rm, Tv, Fc, out);
}

// round 16
// speedup vs baseline: 1.6373x; 1.6373x over previous
#include <cuda_runtime.h>
#include <math.h>

#define BATCH 2
#define NP    4096
#define HH    128
#define WW    128
#define KK    8
#define RAD   0.05f
#define RAD2  (RAD * RAD)
#define TILE  8
#define TX    (WW / TILE)    // 16
#define TYN   (HH / TILE)    // 16
#define LPP   4
#define NPIX  (TILE * TILE)  // 64
#define THREADS (NPIX * LPP) // 256
#define PPT   (NP / THREADS) // 16 points per thread
#define CAP0  896            // master list capacity (~2.8x max observed)
#define CAPQ  512            // per-quadrant capacity (~3x max observed)

#define ZINF 3.0e38f

__global__ void __launch_bounds__(THREADS) raster_fused(
        const float* __restrict__ pts,
        const float* __restrict__ Rm,
        const float* __restrict__ Tv,
        const float* __restrict__ Fc,
        float* __restrict__ out) {
    __shared__ float4 sc0[CAP0];      // 14 KB master candidate list
    __shared__ float4 scq[4][CAPQ];   // 32 KB per-quadrant lists
    __shared__ int s_cnt, s_cntq[4];

    const int bx = blockIdx.x, by = blockIdx.y, b = blockIdx.z;
    const int tid = threadIdx.x;
    const int w = tid >> 5, lane = tid & 31;

    if (tid == 0) s_cnt = 0;
    __syncthreads();

    // Uniform per-batch camera params (broadcast loads)
    const float* Rb = Rm + b * 9;
    const float* Tb = Tv + b * 3;
    const float r00 = Rb[0], r01 = Rb[1], r02 = Rb[2];
    const float r10 = Rb[3], r11 = Rb[4], r12 = Rb[5];
    const float r20 = Rb[6], r21 = Rb[7], r22 = Rb[8];
    const float t0 = Tb[0], t1 = Tb[1], t2 = Tb[2];
    const float f  = Fc[b];

    // Tile outer bbox (gx decreases with pixel x); conservative expand by RAD
    const float gx_hi = 1.0f - ((float)(TILE * bx) + 0.5f) * (1.0f / 64.0f) + RAD;
    const float gx_lo = 1.0f - ((float)(TILE * bx + 7) + 0.5f) * (1.0f / 64.0f) - RAD;
    const float gy_hi = 1.0f - ((float)(TILE * by) + 0.5f) * (1.0f / 64.0f) + RAD;
    const float gy_lo = 1.0f - ((float)(TILE * by + 7) + 0.5f) * (1.0f / 64.0f) - RAD;

    // ====== Phase 1: redundant transform; thread owns 16 CONSECUTIVE points ==
    {
        const float4* pb4 = (const float4*)(pts + (size_t)b * NP * 3);
        int p0i = tid * PPT;
#pragma unroll
        for (int it = 0; it < PPT / 4; it++) {
            int pbase = p0i + it * 4;
            int f4 = (pbase * 3) >> 2;        // pbase*3 divisible by 4
            float4 A = pb4[f4 + 0];
            float4 Bv = pb4[f4 + 1];
            float4 C = pb4[f4 + 2];
            float px3[4], py3[4], pz3[4];
            px3[0] = A.x;  py3[0] = A.y;  pz3[0] = A.z;
            px3[1] = A.w;  py3[1] = Bv.x; pz3[1] = Bv.y;
            px3[2] = Bv.z; py3[2] = Bv.w; pz3[2] = C.x;
            px3[3] = C.y;  py3[3] = C.z;  pz3[3] = C.w;
#pragma unroll
            for (int i = 0; i < 4; i++) {
                float p0 = px3[i], p1 = py3[i], p2 = pz3[i];
                // row-vector: v[j] = sum_i p[i]*R[i][j] + T[j]  (same expr as ref)
                float xv = p0 * r00 + p1 * r10 + p2 * r20 + t0;
                float yv = p0 * r01 + p1 * r11 + p2 * r21 + t1;
                float zv = p0 * r02 + p1 * r12 + p2 * r22 + t2;
                float x = f * xv / zv;        // IEEE div, matches reference
                float y = f * yv / zv;
                if (zv > 0.0f && x > gx_lo && x < gx_hi && y > gy_lo && y < gy_hi) {
                    int pos = atomicAdd(&s_cnt, 1);
                    if (pos < CAP0)
                        sc0[pos] = make_float4(x, y, zv, (float)(pbase + i));
                }
            }
        }
    }
    __syncthreads();
    const int n0 = min(s_cnt, CAP0);

    // ====== Phase 1b: partition into quadrant lists (warps 0-3, no atomics) ==
    if (w < 4) {
        int qx = w & 1, qy = w >> 1;
        float bxq = (float)(TILE * bx + qx * 4);
        float byq = (float)(TILE * by + qy * 4);
        float xhi = 1.0f - (bxq + 0.5f) * (1.0f / 64.0f) + RAD;
        float xlo = 1.0f - (bxq + 3.5f) * (1.0f / 64.0f) - RAD;
        float yhi = 1.0f - (byq + 0.5f) * (1.0f / 64.0f) + RAD;
        float ylo = 1.0f - (byq + 3.5f) * (1.0f / 64.0f) - RAD;
        int cnt = 0;
        for (int j0 = 0; j0 < n0; j0 += 32) {
            int j = j0 + lane;
            bool ok = false;
            float4 c = make_float4(0.f, 0.f, 0.f, 0.f);
            if (j < n0) {
                c = sc0[j];
                ok = (c.x > xlo) & (c.x < xhi) & (c.y > ylo) & (c.y < yhi);
            }
            unsigned m = __ballot_sync(0xffffffffu, ok);
            int pos = cnt + __popc(m & ((1u << lane) - 1u));
            if (ok && pos < CAPQ) scq[w][pos] = c;
            cnt += __popc(m);
        }
        if (lane == 0) s_cntq[w] = min(cnt, CAPQ);
    }
    __syncthreads();

    // ====== Phase 2: raster — warp-uniform quadrant, 4 lanes per pixel =======
    const int q   = w >> 1;                  // quadrant of this warp (0..3)
    const int grp = tid >> 2;                // pixel slot 0..63
    const int sub = tid & 3;                 // lane within pixel
    const int pq  = (w & 1) * 8 + (grp & 7); // pixel within 4x4 quadrant (0..15)
    const int lx  = (q & 1) * 4 + (pq & 3);
    const int ly  = (q >> 1) * 4 + (pq >> 2);
    const int n = s_cntq[q];
    const float4* __restrict__ ql = scq[q];

    const int px = bx * TILE + lx;
    const int py = by * TILE + ly;
    const float gx = 1.0f - (px + 0.5f) * (1.0f / 64.0f);
    const float gy = 1.0f - (py + 0.5f) * (1.0f / 64.0f);

    float zb[KK];
#pragma unroll
    for (int k = 0; k < KK; k++) zb[k] = ZINF;

    // ---- Pass 1: branch-free FMNMX ladder, lane scans j%4==sub -------------
    for (int j = sub; j < n; j += LPP) {
        float4 c = ql[j];
        float dx = gx - c.x;
        float dy = gy - c.y;
        float d2 = fmaf(dx, dx, dy * dy);
        float key = (d2 < RAD2) ? c.z : ZINF;
#pragma unroll
        for (int k = 0; k < KK; k++) {
            float lo = fminf(zb[k], key);
            key = fmaxf(zb[k], key);
            zb[k] = lo;
        }
    }

    // ---- merge 4 sorted lists: two bitonic-merge rounds (xor 1, xor 2) ------
#pragma unroll
    for (int d = 1; d <= 2; d <<= 1) {
        float L[KK];
#pragma unroll
        for (int k = 0; k < KK; k++) {
            float bk = __shfl_xor_sync(0xffffffffu, zb[KK - 1 - k], d);
            L[k] = fminf(zb[k], bk);          // lower half of bitonic merge
        }
#define CE(a, b2) { float lo = fminf(L[a], L[b2]); float hi = fmaxf(L[a], L[b2]); L[a] = lo; L[b2] = hi; }
        CE(0, 4) CE(1, 5) CE(2, 6) CE(3, 7)
        CE(0, 2) CE(1, 3) CE(4, 6) CE(5, 7)
        CE(0, 1) CE(2, 3) CE(4, 5) CE(6, 7)
#undef CE
#pragma unroll
        for (int k = 0; k < KK; k++) zb[k] = L[k];
    }
    const float z7 = zb[KK - 1];

    float db[KK], ib[KK];
#pragma unroll
    for (int k = 0; k < KK; k++) { db[k] = -1.0f; ib[k] = -1.0f; }

    // ---- Pass 2: sparse equality fill of d2/idx (z values distinct) ---------
    for (int j = sub; j < n; j += LPP) {
        float4 c = ql[j];
        float dx = gx - c.x;
        float dy = gy - c.y;
        float d2 = fmaf(dx, dx, dy * dy);
        if (d2 < RAD2 && c.z <= z7) {
#pragma unroll
            for (int k = 0; k < KK; k++) {
                if (c.z == zb[k]) { db[k] = d2; ib[k] = c.w; }
            }
        }
    }

    // ---- combine lane fills (unfilled = -1, filled >= 0 => max) -------------
#pragma unroll
    for (int d = 1; d <= 2; d <<= 1) {
#pragma unroll
        for (int k = 0; k < KK; k++) {
            db[k] = fmaxf(db[k], __shfl_xor_sync(0xffffffffu, db[k], d));
            ib[k] = fmaxf(ib[k], __shfl_xor_sync(0xffffffffu, ib[k], d));
        }
    }

    // ---- Output: [idx | zbuf | dists], each [B,H,W,K]; lanes split k --------
    const int N = BATCH * HH * WW * KK;
    const int obase = ((b * HH + py) * WW + px) * KK;
#pragma unroll
    for (int k2 = 0; k2 < KK / LPP; k2++) {
        int k = sub * (KK / LPP) + k2;
        bool v = zb[k] < ZINF;
        out[obase + k]         = v ? ib[k] : -1.0f;
        out[N + obase + k]     = v ? zb[k] : -1.0f;
        out[2 * N + obase + k] = v ? db[k] : -1.0f;
    }
}

// ---------------------------------------------------------------------------
extern "C" void kernel_launch(void* const* d_in, const int* in_sizes, int n_in,
                              void* d_out, int out_size) {
    const float* pts = (const float*)d_in[0];
    const float* Rm  = (const float*)d_in[1];
    const float* Tv  = (const float*)d_in[2];
    const float* Fc  = (const float*)d_in[3];
    float* out = (float*)d_out;

    raster_fused<<<dim3(TX, TYN, BATCH), THREADS>>>(pts, Rm, Tv, Fc, out);
}

// round 17
// speedup vs baseline: 1.6612x; 1.0146x over previous
#include <cuda_runtime.h>
#include <math.h>

#define BATCH 2
#define NP    4096
#define HH    128
#define WW    128
#define KK    8
#define RAD   0.05f
#define RAD2  (RAD * RAD)
#define MARG  1e-5f
#define TILE  8
#define TX    (WW / TILE)    // 16
#define TYN   (HH / TILE)    // 16
#define LPP   4
#define NPIX  (TILE * TILE)  // 64
#define THREADS (NPIX * LPP) // 256
#define PPT   (NP / THREADS) // 16 points per thread
#define CAP0  896            // master list capacity
#define CAPQ  512            // per-quadrant capacity (2 segments of 256)
#define HALFQ (CAPQ / 2)

#define ZINF 3.0e38f

__global__ void __launch_bounds__(THREADS) raster_fused(
        const float* __restrict__ pts,
        const float* __restrict__ Rm,
        const float* __restrict__ Tv,
        const float* __restrict__ Fc,
        float* __restrict__ out) {
    __shared__ float4 sc0[CAP0];      // 14 KB master candidate list
    __shared__ float4 scq[4][CAPQ];   // 32 KB per-quadrant lists (2 segs each)
    __shared__ int s_cnt, s_cntq[8];  // [q*2+seg]

    const int bx = blockIdx.x, by = blockIdx.y, b = blockIdx.z;
    const int tid = threadIdx.x;
    const int w = tid >> 5, lane = tid & 31;

    if (tid == 0) s_cnt = 0;
    __syncthreads();

    // Uniform per-batch camera params (broadcast loads)
    const float* Rb = Rm + b * 9;
    const float* Tb = Tv + b * 3;
    const float r00 = Rb[0], r01 = Rb[1], r02 = Rb[2];
    const float r10 = Rb[3], r11 = Rb[4], r12 = Rb[5];
    const float r20 = Rb[6], r21 = Rb[7], r22 = Rb[8];
    const float t0 = Tb[0], t1 = Tb[1], t2 = Tb[2];
    const float f  = Fc[b];

    // Tile outer bbox (NDC, expanded by RAD + MARG) for the view-space test
    const float bxh = 1.0f - ((float)(TILE * bx) + 0.5f) * (1.0f / 64.0f) + RAD + MARG;
    const float bxl = 1.0f - ((float)(TILE * bx + 7) + 0.5f) * (1.0f / 64.0f) - RAD - MARG;
    const float byh = 1.0f - ((float)(TILE * by) + 0.5f) * (1.0f / 64.0f) + RAD + MARG;
    const float byl = 1.0f - ((float)(TILE * by + 7) + 0.5f) * (1.0f / 64.0f) - RAD - MARG;

    // ====== Phase 1: transform with DIV-FREE rejection; divs only on accept ==
    {
        const float4* pb4 = (const float4*)(pts + (size_t)b * NP * 3);
        int p0i = tid * PPT;
#pragma unroll
        for (int it = 0; it < PPT / 4; it++) {
            int pbase = p0i + it * 4;
            int f4 = (pbase * 3) >> 2;        // pbase*3 divisible by 4
            float4 A = pb4[f4 + 0];
            float4 Bv = pb4[f4 + 1];
            float4 C = pb4[f4 + 2];
            float px3[4], py3[4], pz3[4];
            px3[0] = A.x;  py3[0] = A.y;  pz3[0] = A.z;
            px3[1] = A.w;  py3[1] = Bv.x; pz3[1] = Bv.y;
            px3[2] = Bv.z; py3[2] = Bv.w; pz3[2] = C.x;
            px3[3] = C.y;  py3[3] = C.z;  pz3[3] = C.w;
#pragma unroll
            for (int i = 0; i < 4; i++) {
                float p0 = px3[i], p1 = py3[i], p2 = pz3[i];
                // row-vector: v[j] = sum_i p[i]*R[i][j] + T[j]  (same expr as ref)
                float xv = p0 * r00 + p1 * r10 + p2 * r20 + t0;
                float yv = p0 * r01 + p1 * r11 + p2 * r21 + t1;
                float zv = p0 * r02 + p1 * r12 + p2 * r22 + t2;
                float fxv = f * xv;           // reference computes (f*xv)/zv
                float fyv = f * yv;
                // view-space bbox test (valid for zv>0): x>lo <=> f*xv > lo*zv
                bool ok = (zv > 0.0f)
                        & (fxv > bxl * zv) & (fxv < bxh * zv)
                        & (fyv > byl * zv) & (fyv < byh * zv);
                if (ok) {
                    float x = fxv / zv;       // IEEE div — bitwise same as ref
                    float y = fyv / zv;
                    int pos = atomicAdd(&s_cnt, 1);
                    if (pos < CAP0)
                        sc0[pos] = make_float4(x, y, zv, (float)(pbase + i));
                }
            }
        }
    }
    __syncthreads();
    const int n0 = min(s_cnt, CAP0);

    // ====== Phase 1b: partition; 8 warps = 4 quadrants x 2 half-segments =====
    {
        const int q = w & 3, half = w >> 2;
        const int js = half ? (n0 >> 1) : 0;
        const int je = half ? n0 : (n0 >> 1);
        int qx = q & 1, qy = q >> 1;
        float bxq = (float)(TILE * bx + qx * 4);
        float byq = (float)(TILE * by + qy * 4);
        float xhi = 1.0f - (bxq + 0.5f) * (1.0f / 64.0f) + RAD;
        float xlo = 1.0f - (bxq + 3.5f) * (1.0f / 64.0f) - RAD;
        float yhi = 1.0f - (byq + 0.5f) * (1.0f / 64.0f) + RAD;
        float ylo = 1.0f - (byq + 3.5f) * (1.0f / 64.0f) - RAD;
        float4* dst = &scq[q][half * HALFQ];
        int cnt = 0;
        for (int j0 = js; j0 < je; j0 += 32) {
            int j = j0 + lane;
            bool okq = false;
            float4 c = make_float4(0.f, 0.f, 0.f, 0.f);
            if (j < je) {
                c = sc0[j];
                okq = (c.x > xlo) & (c.x < xhi) & (c.y > ylo) & (c.y < yhi);
            }
            unsigned m = __ballot_sync(0xffffffffu, okq);
            int pos = cnt + __popc(m & ((1u << lane) - 1u));
            if (okq && pos < HALFQ) dst[pos] = c;
            cnt += __popc(m);
        }
        if (lane == 0) s_cntq[q * 2 + half] = min(cnt, HALFQ);
    }
    __syncthreads();

    // ====== Phase 2: raster — warp-uniform quadrant, 4 lanes per pixel =======
    const int q   = w >> 1;                  // quadrant of this warp (0..3)
    const int grp = tid >> 2;                // pixel slot 0..63
    const int sub = tid & 3;                 // lane within pixel
    const int pq  = (w & 1) * 8 + (grp & 7); // pixel within 4x4 quadrant (0..15)
    const int lx  = (q & 1) * 4 + (pq & 3);
    const int ly  = (q >> 1) * 4 + (pq >> 2);
    const int nA = s_cntq[q * 2 + 0];
    const int nB = s_cntq[q * 2 + 1];
    const float4* __restrict__ qlA = scq[q];
    const float4* __restrict__ qlB = scq[q] + HALFQ;

    const int px = bx * TILE + lx;
    const int py = by * TILE + ly;
    const float gx = 1.0f - (px + 0.5f) * (1.0f / 64.0f);
    const float gy = 1.0f - (py + 0.5f) * (1.0f / 64.0f);

    float zb[KK];
#pragma unroll
    for (int k = 0; k < KK; k++) zb[k] = ZINF;

    // ---- Pass 1: branch-free FMNMX ladder over both segments ---------------
#pragma unroll 1
    for (int seg = 0; seg < 2; seg++) {
        const float4* ql = seg ? qlB : qlA;
        const int n = seg ? nB : nA;
        for (int j = sub; j < n; j += LPP) {
            float4 c = ql[j];
            float dx = gx - c.x;
            float dy = gy - c.y;
            float d2 = fmaf(dx, dx, dy * dy);
            float key = (d2 < RAD2) ? c.z : ZINF;
#pragma unroll
            for (int k = 0; k < KK; k++) {
                float lo = fminf(zb[k], key);
                key = fmaxf(zb[k], key);
                zb[k] = lo;
            }
        }
    }

    // ---- merge 4 sorted lists: two bitonic-merge rounds (xor 1, xor 2) ------
#pragma unroll
    for (int d = 1; d <= 2; d <<= 1) {
        float L[KK];
#pragma unroll
        for (int k = 0; k < KK; k++) {
            float bk = __shfl_xor_sync(0xffffffffu, zb[KK - 1 - k], d);
            L[k] = fminf(zb[k], bk);          // lower half of bitonic merge
        }
#define CE(a, b2) { float lo = fminf(L[a], L[b2]); float hi = fmaxf(L[a], L[b2]); L[a] = lo; L[b2] = hi; }
        CE(0, 4) CE(1, 5) CE(2, 6) CE(3, 7)
        CE(0, 2) CE(1, 3) CE(4, 6) CE(5, 7)
        CE(0, 1) CE(2, 3) CE(4, 5) CE(6, 7)
#undef CE
#pragma unroll
        for (int k = 0; k < KK; k++) zb[k] = L[k];
    }
    const float z7 = zb[KK - 1];

    float db[KK], ib[KK];
#pragma unroll
    for (int k = 0; k < KK; k++) { db[k] = -1.0f; ib[k] = -1.0f; }

    // ---- Pass 2: sparse equality fill of d2/idx (z values distinct) ---------
#pragma unroll 1
    for (int seg = 0; seg < 2; seg++) {
        const float4* ql = seg ? qlB : qlA;
        const int n = seg ? nB : nA;
        for (int j = sub; j < n; j += LPP) {
            float4 c = ql[j];
            float dx = gx - c.x;
            float dy = gy - c.y;
            float d2 = fmaf(dx, dx, dy * dy);
            if (d2 < RAD2 && c.z <= z7) {
#pragma unroll
                for (int k = 0; k < KK; k++) {
                    if (c.z == zb[k]) { db[k] = d2; ib[k] = c.w; }
                }
            }
        }
    }

    // ---- combine lane fills (unfilled = -1, filled >= 0 => max) -------------
#pragma unroll
    for (int d = 1; d <= 2; d <<= 1) {
#pragma unroll
        for (int k = 0; k < KK; k++) {
            db[k] = fmaxf(db[k], __shfl_xor_sync(0xffffffffu, db[k], d));
            ib[k] = fmaxf(ib[k], __shfl_xor_sync(0xffffffffu, ib[k], d));
        }
    }

    // ---- Output: [idx | zbuf | dists], each [B,H,W,K]; lanes split k --------
    const int N = BATCH * HH * WW * KK;
    const int obase = ((b * HH + py) * WW + px) * KK;
#pragma unroll
    for (int k2 = 0; k2 < KK / LPP; k2++) {
        int k = sub * (KK / LPP) + k2;
        bool v = zb[k] < ZINF;
        out[obase + k]         = v ? ib[k] : -1.0f;
        out[N + obase + k]     = v ? zb[k] : -1.0f;
        out[2 * N + obase + k] = v ? db[k] : -1.0f;
    }
}

// ---------------------------------------------------------------------------
extern "C" void kernel_launch(void* const* d_in, const int* in_sizes, int n_in,
                              void* d_out, int out_size) {
    const float* pts = (const float*)d_in[0];
    const float* Rm  = (const float*)d_in[1];
    const float* Tv  = (const float*)d_in[2];
    const float* Fc  = (const float*)d_in[3];
    float* out = (float*)d_out;

    raster_fused<<<dim3(TX, TYN, BATCH), THREADS>>>(pts, Rm, Tv, Fc, out);
}